// round 1
// baseline (speedup 1.0000x reference)
#include <cuda_runtime.h>
#include <math.h>

#define Bn 4
#define Cc 256
#define Hh 64
#define Wp 64
#define Nn 4096
#define Mm (Bn*Nn)   // 16384

// ---------------- scratch (device globals; no allocation) ----------------
__device__ float d_xT[Bn*Nn*Cc];   // x transposed to [B,N,C]
__device__ float d_q [Bn*Nn*Cc];   // theta rows
__device__ float d_kk[Bn*Nn*Cc];   // phi rows
__device__ float d_gg[Bn*Nn*Cc];   // g rows
__device__ float d_y [Bn*Nn*Cc];   // attention output [B,N,C]
__device__ float d_wy[Bn*Nn*Cc];   // W_y (NHWC)
__device__ float d_t1[Bn*Nn*Cc];
__device__ float d_t2[Bn*Nn*Cc];
__device__ float d_mk[Bn*Nn];
__device__ int   d_act[Bn*Nn];
__device__ int   d_cnt[Bn];
__device__ float d_w1x1[4*Cc*Cc];      // gT, thetaT, phiT, WT  ([c][o])
__device__ float d_wcv[6*9*Cc*Cc];     // conv weights [conv][tap][c][o]
__device__ float d_part[Bn*32*Cc*2];
__device__ float d_mean[Bn*Cc];
__device__ float d_rstd[Bn*Cc];

// ---------------- weight transpose ----------------
__global__ void k_wt(const float* __restrict__ gw, const float* __restrict__ tw,
                     const float* __restrict__ pw, const float* __restrict__ WW,
                     const float* __restrict__ rw1, const float* __restrict__ rw2) {
    __shared__ float tile[32][33];
    int z = blockIdx.z;
    int o0 = blockIdx.x*32, c0 = blockIdx.y*32;
    int tx = threadIdx.x, ty = threadIdx.y;
    if (z < 4) {
        const float* src = (z==0) ? gw : (z==1) ? tw : (z==2) ? pw : WW;
        tile[ty][tx] = src[(o0+ty)*Cc + c0+tx];
        __syncthreads();
        d_w1x1[z*Cc*Cc + (c0+ty)*Cc + (o0+tx)] = tile[tx][ty];
    } else {
        int id = z-4; int cv = id/9, tap = id%9;
        int i = cv>>1; const float* rw = (cv&1) ? rw2 : rw1;
        tile[ty][tx] = rw[(((i*Cc)+(o0+ty))*Cc + (c0+tx))*9 + tap];
        __syncthreads();
        d_wcv[(cv*9+tap)*Cc*Cc + (c0+ty)*Cc + (o0+tx)] = tile[tx][ty];
    }
}

// ---------------- x: NCHW -> [B,N,C] ----------------
__global__ void k_xt(const float* __restrict__ x) {
    __shared__ float tile[32][33];
    int b = blockIdx.z; int n0 = blockIdx.x*32, c0 = blockIdx.y*32;
    int tx = threadIdx.x, ty = threadIdx.y;
    tile[ty][tx] = x[((size_t)(b*Cc) + c0+ty)*Nn + n0+tx];
    __syncthreads();
    d_xT[((size_t)(b*Nn) + n0+ty)*Cc + c0+tx] = tile[tx][ty];
}

// ---------------- mask + deterministic active-key compaction ----------------
__global__ void k_mask(const float* __restrict__ mask) {
    int b = blockIdx.x, t = threadIdx.x;
    __shared__ int sc[1024];
    const float* mb = mask + b*32*32;
    int flag[4]; int cnt = 0;
    #pragma unroll
    for (int i=0;i<4;i++){
        int n = t*4+i; int h = n>>6, w = n&63;
        float fy = h*0.5f - 0.25f, fx = w*0.5f - 0.25f;
        int y0 = (int)floorf(fy), x0 = (int)floorf(fx);
        float wy1 = fy - (float)y0, wx1 = fx - (float)x0;
        int y0c = min(max(y0,0),31), y1c = min(max(y0+1,0),31);
        int x0c = min(max(x0,0),31), x1c = min(max(x0+1,0),31);
        float v = (mb[y0c*32+x0c]*(1.f-wx1) + mb[y0c*32+x1c]*wx1)*(1.f-wy1)
                + (mb[y1c*32+x0c]*(1.f-wx1) + mb[y1c*32+x1c]*wx1)*wy1;
        float mv = (v > 0.f) ? 1.f : v;
        float a = 1.f - mv;
        float tmp = 1.f - mb[(h>>1)*32 + (w>>1)];
        float m = a * tmp;
        d_mk[b*Nn + n] = m;
        flag[i] = (m > 0.5f) ? 1 : 0;
        cnt += flag[i];
    }
    sc[t] = cnt; __syncthreads();
    for (int s=1; s<1024; s<<=1){
        int v = (t >= s) ? sc[t-s] : 0;
        __syncthreads();
        sc[t] += v;
        __syncthreads();
    }
    int base = sc[t] - cnt;
    #pragma unroll
    for (int i=0;i<4;i++) if (flag[i]) d_act[b*Nn + (base++)] = t*4+i;
    if (t == 1023) d_cnt[b] = sc[1023];
}

// ---------------- SGEMM: C[M,256] = A[M,256] * Bw[256,256] + bias ----------------
__global__ void __launch_bounds__(256) k_gemm(const float* __restrict__ A,
                                              const float* __restrict__ Bw,
                                              const float* __restrict__ bias,
                                              float* __restrict__ Cout) {
    __shared__ float As[16][128];
    __shared__ float Bs[16][128];
    int t = threadIdx.x;
    int tx = t & 15, ty = t >> 4;
    int m0 = blockIdx.y * 128, n0 = blockIdx.x * 128;
    float acc[8][8] = {};
    for (int k0 = 0; k0 < 256; k0 += 16) {
        #pragma unroll
        for (int i=0;i<2;i++){
            int f4 = t + i*256;
            int row = f4 >> 2, c4 = (f4 & 3)*4;
            float4 v = *(const float4*)&A[(size_t)(m0+row)*256 + k0 + c4];
            As[c4+0][row]=v.x; As[c4+1][row]=v.y; As[c4+2][row]=v.z; As[c4+3][row]=v.w;
        }
        #pragma unroll
        for (int i=0;i<2;i++){
            int f4 = t + i*256;
            int row = f4 >> 5, c4 = (f4 & 31)*4;
            *(float4*)&Bs[row][c4] = *(const float4*)&Bw[(k0+row)*256 + n0 + c4];
        }
        __syncthreads();
        #pragma unroll
        for (int kk=0; kk<16; kk++){
            float a[8], bb[8];
            *(float4*)&a[0]  = *(float4*)&As[kk][ty*8];
            *(float4*)&a[4]  = *(float4*)&As[kk][ty*8+4];
            *(float4*)&bb[0] = *(float4*)&Bs[kk][tx*8];
            *(float4*)&bb[4] = *(float4*)&Bs[kk][tx*8+4];
            #pragma unroll
            for (int r=0;r<8;r++)
                #pragma unroll
                for (int c=0;c<8;c++) acc[r][c] += a[r]*bb[c];
        }
        __syncthreads();
    }
    #pragma unroll
    for (int r=0;r<8;r++){
        int m = m0 + ty*8 + r;
        #pragma unroll
        for (int c=0;c<8;c+=4){
            int n = n0 + tx*8 + c;
            float4 v;
            v.x = acc[r][c]   + bias[n];
            v.y = acc[r][c+1] + bias[n+1];
            v.z = acc[r][c+2] + bias[n+2];
            v.w = acc[r][c+3] + bias[n+3];
            *(float4*)&Cout[(size_t)m*256 + n] = v;
        }
    }
}

// ---------------- 3x3 reflect conv as 9 fused tap-GEMMs ----------------
__device__ __forceinline__ int refl(int i, int n){ return i<0 ? -i : (i>=n ? 2*n-2-i : i); }

__global__ void __launch_bounds__(256) k_conv3(const float* __restrict__ A,
                                               const float* __restrict__ Wt,  // [9][256][256]
                                               const float* __restrict__ bias,
                                               float* __restrict__ Cout) {
    __shared__ float As[16][128];
    __shared__ float Bs[16][128];
    int t = threadIdx.x, tx = t & 15, ty = t >> 4;
    int m0 = blockIdx.y * 128, n0 = blockIdx.x * 128;
    float acc[8][8] = {};
    for (int tap=0; tap<9; tap++){
        int dy = tap/3 - 1, dx = tap%3 - 1;
        const float* Wb = Wt + tap*Cc*Cc;
        int srow[2];
        #pragma unroll
        for (int i=0;i<2;i++){
            int f4 = t + i*256; int row = f4 >> 2;
            int mg = m0 + row;
            int b = mg >> 12, p = mg & 4095, h = p >> 6, w = p & 63;
            srow[i] = (b<<12) + (refl(h+dy,64)<<6) + refl(w+dx,64);
        }
        for (int k0=0; k0<256; k0+=16){
            #pragma unroll
            for (int i=0;i<2;i++){
                int f4 = t + i*256;
                int row = f4 >> 2, c4 = (f4 & 3)*4;
                float4 v = *(const float4*)&A[(size_t)srow[i]*256 + k0 + c4];
                As[c4+0][row]=v.x; As[c4+1][row]=v.y; As[c4+2][row]=v.z; As[c4+3][row]=v.w;
            }
            #pragma unroll
            for (int i=0;i<2;i++){
                int f4 = t + i*256;
                int row = f4 >> 5, c4 = (f4 & 31)*4;
                *(float4*)&Bs[row][c4] = *(const float4*)&Wb[(k0+row)*256 + n0 + c4];
            }
            __syncthreads();
            #pragma unroll
            for (int kk=0; kk<16; kk++){
                float a[8], bb[8];
                *(float4*)&a[0]  = *(float4*)&As[kk][ty*8];
                *(float4*)&a[4]  = *(float4*)&As[kk][ty*8+4];
                *(float4*)&bb[0] = *(float4*)&Bs[kk][tx*8];
                *(float4*)&bb[4] = *(float4*)&Bs[kk][tx*8+4];
                #pragma unroll
                for (int r=0;r<8;r++)
                    #pragma unroll
                    for (int c=0;c<8;c++) acc[r][c] += a[r]*bb[c];
            }
            __syncthreads();
        }
    }
    #pragma unroll
    for (int r=0;r<8;r++){
        int m = m0 + ty*8 + r;
        #pragma unroll
        for (int c=0;c<8;c+=4){
            int n = n0 + tx*8 + c;
            float4 v;
            v.x = acc[r][c]   + bias[n];
            v.y = acc[r][c+1] + bias[n+1];
            v.z = acc[r][c+2] + bias[n+2];
            v.w = acc[r][c+3] + bias[n+3];
            *(float4*)&Cout[(size_t)m*256 + n] = v;
        }
    }
}

// ---------------- masked-softmax attention over compacted keys ----------------
__global__ void __launch_bounds__(256) k_attn() {
    int b = blockIdx.y; int q0 = blockIdx.x * 16;
    __shared__ float Qs[16][257];
    __shared__ float Ks[16][257];
    __shared__ float Gs[16][257];
    __shared__ float Ss[16][17];
    int t = threadIdx.x;
    for (int i=t; i<16*256; i+=256){
        int r = i >> 8, c = i & 255;
        Qs[r][c] = d_q[((size_t)(b*Nn) + q0 + r)*256 + c];
    }
    int cnt = d_cnt[b];
    int q = t >> 4, lane = t & 15;
    float yacc[16];
    #pragma unroll
    for (int i=0;i<16;i++) yacc[i] = 0.f;
    float rmax = -1e30f, rsum = 0.f;
    __syncthreads();
    for (int j0=0; j0<cnt; j0+=16){
        int jn = min(16, cnt - j0);
        for (int i=t; i<jn*256; i+=256){
            int r = i >> 8, c = i & 255;
            int src = d_act[b*Nn + j0 + r];
            Ks[r][c] = d_kk[((size_t)(b*Nn) + src)*256 + c];
            Gs[r][c] = d_gg[((size_t)(b*Nn) + src)*256 + c];
        }
        __syncthreads();
        float s = -1e30f;
        if (lane < jn){
            s = 0.f;
            #pragma unroll 8
            for (int c2=0; c2<256; c2++) s += Qs[q][c2]*Ks[lane][c2];
        }
        Ss[q][lane] = s;
        __syncthreads();
        float cmax = rmax;
        for (int j=0;j<jn;j++) cmax = fmaxf(cmax, Ss[q][j]);
        float scale = expf(rmax - cmax);
        rsum *= scale;
        #pragma unroll
        for (int i=0;i<16;i++) yacc[i] *= scale;
        for (int j=0;j<jn;j++){
            float pj = expf(Ss[q][j] - cmax);
            rsum += pj;
            #pragma unroll
            for (int i=0;i<16;i++) yacc[i] += pj * Gs[j][lane + i*16];
        }
        rmax = cmax;
        __syncthreads();
    }
    float inv = (rsum > 0.f) ? (1.f/rsum) : 0.f;
    #pragma unroll
    for (int i=0;i<16;i++)
        d_y[((size_t)(b*Nn) + q0 + q)*256 + lane + i*16] = yacc[i]*inv;
}

// ---------------- instance-norm stats ----------------
__global__ void k_stat(const float* __restrict__ buf){
    int ch = blockIdx.x, b = blockIdx.y;  // grid (32, B)
    int c = threadIdx.x;
    const float* p = buf + ((size_t)(b*Nn) + ch*128)*256 + c;
    float s = 0.f, s2 = 0.f;
    for (int r=0;r<128;r++){ float v = p[(size_t)r*256]; s += v; s2 += v*v; }
    d_part[((b*32+ch)*256+c)*2+0] = s;
    d_part[((b*32+ch)*256+c)*2+1] = s2;
}
__global__ void k_statf(){
    int b = blockIdx.x, c = threadIdx.x;
    float s=0.f, s2=0.f;
    for (int k=0;k<32;k++){
        s  += d_part[((b*32+k)*256+c)*2+0];
        s2 += d_part[((b*32+k)*256+c)*2+1];
    }
    float mu = s * (1.f/4096.f);
    float var = s2 * (1.f/4096.f) - mu*mu;
    d_mean[b*256+c] = mu;
    d_rstd[b*256+c] = rsqrtf(var + 1e-5f);
}
__global__ void k_in_relu(const float* __restrict__ in, float* __restrict__ out){
    int i = blockIdx.x*256 + threadIdx.x;
    int c = i & 255; int b = i >> 20;
    float v = (in[i] - d_mean[b*256+c]) * d_rstd[b*256+c];
    out[i] = fmaxf(v, 0.f);
}
__global__ void k_in_add(const float* __restrict__ in, float* __restrict__ io){
    int i = blockIdx.x*256 + threadIdx.x;
    int c = i & 255; int b = i >> 20;
    io[i] += (in[i] - d_mean[b*256+c]) * d_rstd[b*256+c];
}

// ---------------- final blend + NHWC->NCHW ----------------
__global__ void k_blend(const float* __restrict__ x, float* __restrict__ z){
    __shared__ float tile[32][33];
    int b = blockIdx.z; int n0 = blockIdx.x*32, c0 = blockIdx.y*32;
    int tx = threadIdx.x, ty = threadIdx.y;
    tile[ty][tx] = d_wy[((size_t)(b*Nn) + n0+ty)*256 + c0+tx];
    __syncthreads();
    int n = n0 + tx, c = c0 + ty;
    float m = d_mk[b*Nn + n];
    size_t idx = ((size_t)(b*Cc + c))*Nn + n;
    z[idx] = m * x[idx] + (1.f - m) * tile[tx][ty];
}

// ---------------- launch ----------------
extern "C" void kernel_launch(void* const* d_in, const int* in_sizes, int n_in,
                              void* d_out, int out_size) {
    (void)in_sizes; (void)n_in; (void)out_size;
    const float* x    = (const float*)d_in[0];
    const float* mask = (const float*)d_in[1];
    const float* g_w  = (const float*)d_in[2];
    const float* g_b  = (const float*)d_in[3];
    const float* th_w = (const float*)d_in[4];
    const float* th_b = (const float*)d_in[5];
    const float* ph_w = (const float*)d_in[6];
    const float* ph_b = (const float*)d_in[7];
    const float* W_w  = (const float*)d_in[8];
    const float* W_b  = (const float*)d_in[9];
    const float* rw1  = (const float*)d_in[10];
    const float* rb1  = (const float*)d_in[11];
    const float* rw2  = (const float*)d_in[12];
    const float* rb2  = (const float*)d_in[13];
    float* z = (float*)d_out;

    float *pxT, *pq, *pk, *pg, *py, *pwy, *pt1, *pt2, *pw1, *pwc;
    cudaGetSymbolAddress((void**)&pxT, d_xT);
    cudaGetSymbolAddress((void**)&pq,  d_q);
    cudaGetSymbolAddress((void**)&pk,  d_kk);
    cudaGetSymbolAddress((void**)&pg,  d_gg);
    cudaGetSymbolAddress((void**)&py,  d_y);
    cudaGetSymbolAddress((void**)&pwy, d_wy);
    cudaGetSymbolAddress((void**)&pt1, d_t1);
    cudaGetSymbolAddress((void**)&pt2, d_t2);
    cudaGetSymbolAddress((void**)&pw1, d_w1x1);
    cudaGetSymbolAddress((void**)&pwc, d_wcv);

    dim3 t32(32,32);
    k_wt  <<<dim3(8,8,58),  t32>>>(g_w, th_w, ph_w, W_w, rw1, rw2);
    k_xt  <<<dim3(128,8,4), t32>>>(x);
    k_mask<<<4, 1024>>>(mask);

    dim3 gg(2,128);
    k_gemm<<<gg,256>>>(pxT, pw1 + 1*Cc*Cc, th_b, pq);   // theta
    k_gemm<<<gg,256>>>(pxT, pw1 + 2*Cc*Cc, ph_b, pk);   // phi
    k_gemm<<<gg,256>>>(pxT, pw1 + 0*Cc*Cc, g_b,  pg);   // g

    k_attn<<<dim3(256,4),256>>>();

    k_gemm<<<gg,256>>>(py, pw1 + 3*Cc*Cc, W_b, pwy);    // W conv1x1

    for (int i=0;i<3;i++){
        k_conv3<<<gg,256>>>(pwy, pwc + (size_t)(2*i)*9*Cc*Cc, rb1 + i*Cc, pt1);
        k_stat <<<dim3(32,4),256>>>(pt1);
        k_statf<<<4,256>>>();
        k_in_relu<<<16384,256>>>(pt1, pt2);
        k_conv3<<<gg,256>>>(pt2, pwc + (size_t)(2*i+1)*9*Cc*Cc, rb2 + i*Cc, pt1);
        k_stat <<<dim3(32,4),256>>>(pt1);
        k_statf<<<4,256>>>();
        k_in_add<<<16384,256>>>(pt1, pwy);
    }

    k_blend<<<dim3(128,8,4), t32>>>(x, z);
}